// round 14
// baseline (speedup 1.0000x reference)
#include <cuda_runtime.h>
#include <cuda_fp16.h>
#include <cstdint>

// ROI Align, P=7, S=2, SCALE=0.125
// x: (8, 256, 100, 100) fp32   rois: (512, 5) fp32   out: (512, 256, 7, 7) fp32
//
// 1) transpose_kernel (320 thr): NCHW fp32 -> NHWC-256 fp16 slab (41MB).
//    Phase 1 batches 2 work items -> 4 independent LDG.128 in flight/thread
//    (MLP fix: kernel was DRAM-latency-bound at ~3.5 TB/s).
// 2) roi_fp16: block = (roi, bin-half) -> 1024 blocks, ~26KB smem.
//    Warp = one bin x 256 channels; tap = LDG.128 (512B/warp).
//    Horizontal interp fp16 (HFMA2), vertical fp32.

#define C_    256
#define H_    100
#define W_    100
#define HW_   10000
#define R_    512
#define PIXU4 32                    // uint4 per pixel (256ch fp16 = 512B)
#define ROWU4 (W_ * PIXU4)          // 3200
#define TPAD  102                   // transpose smem row pad (words)
#define TTHR  320

// fp16 slab: 8 * 10000 * 128 uints = 40.96 MB
__device__ unsigned int g_xt[8 * HW_ * 128];

__device__ __forceinline__ void axis_terms(float c, int L,
                                           int& lo, int& hi,
                                           float& wlo, float& whi) {
    bool valid = (c > -1.0f) && (c < (float)L);
    float cc = fminf(fmaxf(c, 0.0f), (float)(L - 1));
    int l = (int)floorf(cc);
    if (l > L - 1) l = L - 1;
    int h = min(l + 1, L - 1);
    float frac = cc - (float)l;
    lo = l; hi = h;
    wlo = valid ? (1.0f - frac) : 0.0f;
    whi = valid ? frac : 0.0f;
}

// block = (b, y): 256 channels x 100 px -> fp16 channel-major (permuted).
// slab uint4 (pix, q) packs u={q,q+32,q+64,q+96}; uint u = chans (64*(u>>5)+(u&31), +32).
__global__ void __launch_bounds__(TTHR)
transpose_kernel(const float* __restrict__ x) {
    extern __shared__ unsigned int s2[];   // [u][px], pad 102: 52224 B

    const int y   = blockIdx.x % H_;
    const int b   = blockIdx.x / H_;
    const int tid = threadIdx.x;

    const float* srcb = x + (size_t)b * (C_ * HW_) + y * W_;

    // phase 1: 128 u x 25 x4 = 3200 items, 10/thread, batched x2 -> MLP=4.
#pragma unroll
    for (int base = 0; base < 3200; base += 2 * TTHR) {
        int i0 = base + tid;
        int i1 = i0 + TTHR;
        int u0 = i0 / 25, x40 = i0 - u0 * 25;
        int u1 = i1 / 25, x41 = i1 - u1 * 25;
        int cA0 = ((u0 >> 5) << 6) | (u0 & 31);
        int cA1 = ((u1 >> 5) << 6) | (u1 & 31);

        float4 a0 = __ldg((const float4*)(srcb + (size_t)cA0 * HW_) + x40);
        float4 c0 = __ldg((const float4*)(srcb + (size_t)(cA0 + 32) * HW_) + x40);
        float4 a1 = __ldg((const float4*)(srcb + (size_t)cA1 * HW_) + x41);
        float4 c1 = __ldg((const float4*)(srcb + (size_t)(cA1 + 32) * HW_) + x41);

        __half2 p0 = __floats2half2_rn(a0.x, c0.x);
        __half2 p1 = __floats2half2_rn(a0.y, c0.y);
        __half2 p2 = __floats2half2_rn(a0.z, c0.z);
        __half2 p3 = __floats2half2_rn(a0.w, c0.w);
        unsigned int* sp0 = s2 + u0 * TPAD + 4 * x40;
        *(uint2*)(sp0)     = make_uint2(*(unsigned int*)&p0, *(unsigned int*)&p1);
        *(uint2*)(sp0 + 2) = make_uint2(*(unsigned int*)&p2, *(unsigned int*)&p3);

        __half2 q0 = __floats2half2_rn(a1.x, c1.x);
        __half2 q1 = __floats2half2_rn(a1.y, c1.y);
        __half2 q2 = __floats2half2_rn(a1.z, c1.z);
        __half2 q3 = __floats2half2_rn(a1.w, c1.w);
        unsigned int* sp1 = s2 + u1 * TPAD + 4 * x41;
        *(uint2*)(sp1)     = make_uint2(*(unsigned int*)&q0, *(unsigned int*)&q1);
        *(uint2*)(sp1 + 2) = make_uint2(*(unsigned int*)&q2, *(unsigned int*)&q3);
    }
    __syncthreads();

    // phase 2: lane q gathers u = q+32k (stride-102 LDS, 2-way max), STG.128.
    uint4* dst = (uint4*)g_xt + ((size_t)b * HW_ + (size_t)y * W_) * PIXU4;
#pragma unroll
    for (int j = tid; j < W_ * PIXU4; j += TTHR) {
        int px = j >> 5;
        int q  = j & 31;
        const unsigned int* sp = s2 + q * TPAD + px;
        dst[px * PIXU4 + q] = make_uint4(sp[0],
                                         sp[32 * TPAD],
                                         sp[64 * TPAD],
                                         sp[96 * TPAD]);
    }
}

// block = (roi, bin-half): half 0 -> bins [0,25), half 1 -> bins [25,49).
// 256 threads / 8 warps; warp covers all 256 channels of one bin.
__global__ void __launch_bounds__(256)
roi_fp16(const float* __restrict__ rois, float* __restrict__ out) {
    __shared__ int4 sg[28];           // y: {lo*3200, hi*3200, wy0*.25f32, wy1*.25f32}
                                      // x: {xb*32, h2splat(wx0), h2splat(wx1), 0}
    __shared__ __align__(16) float sout[C_ * 25];   // 25600 B

    const int r    = blockIdx.x >> 1;
    const int half = blockIdx.x & 1;
    const int b0   = half * 25;
    const int nb   = 25 - half;       // 25 or 24 bins
    const int tid  = threadIdx.x;

    const float* roi = rois + (size_t)r * 5;
    float r0 = __ldg(roi + 0);
    float r1 = __ldg(roi + 1);
    float r2 = __ldg(roi + 2);
    float r3 = __ldg(roi + 3);
    float r4 = __ldg(roi + 4);

    const int b = (int)r0;
    const float sx = r1 * 0.125f - 0.5f;
    const float sy = r2 * 0.125f - 0.5f;
    const float bw = (r3 * 0.125f - 0.5f - sx) * (1.0f / 7.0f);
    const float bh = (r4 * 0.125f - 0.5f - sy) * (1.0f / 7.0f);

    if (tid < 14) {
        int s = tid;
        float pos = fmaf((float)(s >> 1) + ((s & 1) ? 0.75f : 0.25f), bh, sy);
        int lo, hi; float w0, w1;
        axis_terms(pos, H_, lo, hi, w0, w1);
        sg[s] = make_int4(lo * ROWU4, hi * ROWU4,
                          __float_as_int(w0 * 0.25f), __float_as_int(w1 * 0.25f));
    } else if (tid >= 16 && tid < 30) {
        int s2i = tid - 16;
        float pos = fmaf((float)(s2i >> 1) + ((s2i & 1) ? 0.75f : 0.25f), bw, sx);
        int lo, hi; float w0, w1;
        axis_terms(pos, W_, lo, hi, w0, w1);
        int xb; float v0, v1;
        if (lo == W_ - 1) { xb = W_ - 2; v0 = 0.0f; v1 = w0 + w1; }
        else              { xb = lo;     v0 = w0;   v1 = w1; }
        __half2 s0 = __float2half2_rn(v0);
        __half2 s1 = __float2half2_rn(v1);
        sg[14 + s2i] = make_int4(xb * PIXU4,
                                 *(int*)&s0, *(int*)&s1, 0);
    }
    __syncthreads();

    const int warp = tid >> 5;
    const int lane = tid & 31;
    const uint4* base = (const uint4*)g_xt + (size_t)b * (HW_ * PIXU4) + lane;

    for (int bl = warp; bl < nb; bl += 8) {
        int bin = b0 + bl;
        int ph = (bin * 147) >> 10;       // bin / 7 for bin < 49
        int pw = bin - ph * 7;

        int4 gy0 = sg[2 * ph];
        int4 gy1 = sg[2 * ph + 1];
        int4 gx0 = sg[14 + 2 * pw];
        int4 gx1 = sg[14 + 2 * pw + 1];

        const int xoff = gx0.x;
        const int dx   = gx1.x - gx0.x;
        const __half2 w0s = *(__half2*)&gx0.y;
        const __half2 w1s = *(__half2*)&gx0.z;
        const __half2 w2s = *(__half2*)&gx1.y;
        const __half2 w3s = *(__half2*)&gx1.z;

        const int   roff[4] = {gy0.x, gy0.y, gy1.x, gy1.y};
        const float wy[4]   = {__int_as_float(gy0.z), __int_as_float(gy0.w),
                               __int_as_float(gy1.z), __int_as_float(gy1.w)};

        float acc[8] = {0.f, 0.f, 0.f, 0.f, 0.f, 0.f, 0.f, 0.f};

#pragma unroll
        for (int rr = 0; rr < 4; rr++) {
            const uint4* pr = base + roff[rr] + xoff;
            uint4 t0 = __ldg(pr);
            uint4 t1 = __ldg(pr + PIXU4);
            uint4 t2 = __ldg(pr + dx);
            uint4 t3 = __ldg(pr + dx + PIXU4);
            const __half2* a0 = (const __half2*)&t0;
            const __half2* a1 = (const __half2*)&t1;
            const __half2* a2 = (const __half2*)&t2;
            const __half2* a3 = (const __half2*)&t3;
            float wyr = wy[rr];
#pragma unroll
            for (int m = 0; m < 4; m++) {
                __half2 hv = __hmul2(w0s, a0[m]);
                hv = __hfma2(w1s, a1[m], hv);
                hv = __hfma2(w2s, a2[m], hv);
                hv = __hfma2(w3s, a3[m], hv);
                float2 f2 = __half22float2(hv);
                acc[2 * m]     = fmaf(wyr, f2.x, acc[2 * m]);
                acc[2 * m + 1] = fmaf(wyr, f2.y, acc[2 * m + 1]);
            }
        }

        // acc[j] is channel 32j + lane; sout[c][bl] stride 25 (odd) -> bank-free
        float* so = sout + lane * 25 + bl;
#pragma unroll
        for (int j = 0; j < 8; j++)
            so[j * (32 * 25)] = acc[j];
    }
    __syncthreads();

    // copy: c-major, 25 slots per channel (guard bl < nb for half=1)
    float* op = out + (size_t)r * (C_ * 49) + b0;
    for (int i = tid; i < C_ * 25; i += 256) {
        int c  = i / 25;                 // constant divisor -> mul/shift
        int bl = i - c * 25;
        if (bl < nb)
            op[c * 49 + bl] = sout[i];
    }
}

extern "C" void kernel_launch(void* const* d_in, const int* in_sizes, int n_in,
                              void* d_out, int out_size) {
    const float* x    = (const float*)d_in[0];
    const float* rois = (const float*)d_in[1];
    float* out = (float*)d_out;

    const int tsmem = 128 * TPAD * 4;         // 52224 B
    cudaFuncSetAttribute(transpose_kernel,
                         cudaFuncAttributeMaxDynamicSharedMemorySize, tsmem);

    transpose_kernel<<<8 * H_, TTHR, tsmem>>>(x);
    roi_fp16<<<R_ * 2, 256>>>(rois, out);
}

// round 17
// speedup vs baseline: 1.1594x; 1.1594x over previous
#include <cuda_runtime.h>
#include <cuda_fp16.h>
#include <cstdint>

// ROI Align, P=7, S=2, SCALE=0.125
// x: (8, 256, 100, 100) fp32   rois: (512, 5) fp32   out: (512, 256, 7, 7) fp32
//
// 1) transpose_kernel (320 thr): NCHW fp32 -> NHWC-256 fp16 slab (41MB).
//    Pipelined: 5 chunks x 20 px, double-buffered smem; chunk c+1 LDGs issued
//    before chunk c's STS/STG so DRAM read+write streams overlap.
//    Staging col v = 4(u&31)+(u>>5), row pad 132 -> phase2 is one LDS.128 +
//    one STG.128 per uint4; slab layout bit-identical to R12:
//    uint4 (pix,q) = u {q,q+32,q+64,q+96}; uint u = chans (64*(u>>5)+(u&31), +32).
// 2) roi_fp16 (R12 version): block = roi. Warp = one bin x 256 channels;
//    tap = LDG.128 (512B/warp). Horizontal interp fp16 (HFMA2), vertical fp32.

#define C_    256
#define H_    100
#define W_    100
#define HW_   10000
#define R_    512
#define PIXU4 32                    // uint4 per pixel (256ch fp16 = 512B)
#define ROWU4 (W_ * PIXU4)          // 3200
#define PADU  132                   // staging row stride (words), 16B-aligned
#define TTHR  320

// fp16 slab: 8 * 10000 * 128 uints = 40.96 MB
__device__ unsigned int g_xt[8 * HW_ * 128];

__device__ __forceinline__ void axis_terms(float c, int L,
                                           int& lo, int& hi,
                                           float& wlo, float& whi) {
    bool valid = (c > -1.0f) && (c < (float)L);
    float cc = fminf(fmaxf(c, 0.0f), (float)(L - 1));
    int l = (int)floorf(cc);
    if (l > L - 1) l = L - 1;
    int h = min(l + 1, L - 1);
    float frac = cc - (float)l;
    lo = l; hi = h;
    wlo = valid ? (1.0f - frac) : 0.0f;
    whi = valid ? frac : 0.0f;
}

__device__ __forceinline__ unsigned int packh2(float a, float b) {
    __half2 h = __floats2half2_rn(a, b);
    return *(unsigned int*)&h;
}

// block = (b, y). 5 chunks of 20 px; item (u, xl): u in [0,128), xl in [0,5).
__global__ void __launch_bounds__(TTHR)
transpose_kernel(const float* __restrict__ x) {
    __shared__ unsigned int sbuf[2][20 * PADU];   // 2 x 10560 B

    const int y   = blockIdx.x % H_;
    const int b   = blockIdx.x / H_;
    const int tid = threadIdx.x;

    const float* srcb = x + (size_t)b * (C_ * HW_) + y * W_;

    // per-thread items: i = tid, tid+320  (640 items/chunk, exactly 2 each)
    int u0 = tid / 5,         xl0 = tid - 5 * u0;
    int i1 = tid + TTHR;
    int u1 = i1 / 5,          xl1 = i1 - 5 * u1;
    const float4* pa0 = (const float4*)(srcb + (size_t)(((u0 >> 5) << 6) | (u0 & 31)) * HW_);
    const float4* pc0 = pa0 + 8 * HW_;            // +32 channels (8*HW float4s)
    const float4* pa1 = (const float4*)(srcb + (size_t)(((u1 >> 5) << 6) | (u1 & 31)) * HW_);
    const float4* pc1 = pa1 + 8 * HW_;
    const int v0 = ((u0 & 31) << 2) | (u0 >> 5);
    const int v1 = ((u1 & 31) << 2) | (u1 >> 5);

    // prefetch chunk 0
    float4 ra0 = __ldg(pa0 + xl0), rc0 = __ldg(pc0 + xl0);
    float4 ra1 = __ldg(pa1 + xl1), rc1 = __ldg(pc1 + xl1);

#pragma unroll
    for (int c = 0; c < 5; c++) {
        float4 na0, nc0, na1, nc1;
        if (c < 4) {                        // issue next chunk's loads first
            int xb = 5 * (c + 1);
            na0 = __ldg(pa0 + xb + xl0); nc0 = __ldg(pc0 + xb + xl0);
            na1 = __ldg(pa1 + xb + xl1); nc1 = __ldg(pc1 + xb + xl1);
        }

        unsigned int* buf = sbuf[c & 1];
        {
            unsigned int* s0 = buf + (4 * xl0) * PADU + v0;
            s0[0 * PADU] = packh2(ra0.x, rc0.x);
            s0[1 * PADU] = packh2(ra0.y, rc0.y);
            s0[2 * PADU] = packh2(ra0.z, rc0.z);
            s0[3 * PADU] = packh2(ra0.w, rc0.w);
            unsigned int* s1 = buf + (4 * xl1) * PADU + v1;
            s1[0 * PADU] = packh2(ra1.x, rc1.x);
            s1[1 * PADU] = packh2(ra1.y, rc1.y);
            s1[2 * PADU] = packh2(ra1.z, rc1.z);
            s1[3 * PADU] = packh2(ra1.w, rc1.w);
        }
        __syncthreads();

        // phase2: 640 uint4; j -> (px = j>>5 local, q = j&31); LDS.128 + STG.128
        uint4* dst = (uint4*)g_xt
                   + ((size_t)b * HW_ + (size_t)(y * W_ + 20 * c)) * PIXU4;
#pragma unroll
        for (int k = 0; k < 2; k++) {
            int j  = tid + k * TTHR;
            int q  = j & 31;
            int px = j >> 5;
            dst[px * PIXU4 + q] = *(const uint4*)(buf + px * PADU + 4 * q);
        }
        __syncthreads();

        ra0 = na0; rc0 = nc0; ra1 = na1; rc1 = nc1;
    }
}

// block = roi, 256 threads / 8 warps over 49 bins; warp covers all 256 ch.
__global__ void __launch_bounds__(256)
roi_fp16(const float* __restrict__ rois, float* __restrict__ out) {
    __shared__ int4 sg[28];           // y: {lo*3200, hi*3200, wy0*.25f32, wy1*.25f32}
                                      // x: {xb*32, h2splat(wx0), h2splat(wx1), 0}
    extern __shared__ __align__(16) float sout[];   // 256*49 floats = 50176B

    const int r   = blockIdx.x;
    const int tid = threadIdx.x;

    const float* roi = rois + (size_t)r * 5;
    float r0 = __ldg(roi + 0);
    float r1 = __ldg(roi + 1);
    float r2 = __ldg(roi + 2);
    float r3 = __ldg(roi + 3);
    float r4 = __ldg(roi + 4);

    const int b = (int)r0;
    const float sx = r1 * 0.125f - 0.5f;
    const float sy = r2 * 0.125f - 0.5f;
    const float bw = (r3 * 0.125f - 0.5f - sx) * (1.0f / 7.0f);
    const float bh = (r4 * 0.125f - 0.5f - sy) * (1.0f / 7.0f);

    if (tid < 14) {
        int s = tid;
        float pos = fmaf((float)(s >> 1) + ((s & 1) ? 0.75f : 0.25f), bh, sy);
        int lo, hi; float w0, w1;
        axis_terms(pos, H_, lo, hi, w0, w1);
        sg[s] = make_int4(lo * ROWU4, hi * ROWU4,
                          __float_as_int(w0 * 0.25f), __float_as_int(w1 * 0.25f));
    } else if (tid >= 16 && tid < 30) {
        int s2i = tid - 16;
        float pos = fmaf((float)(s2i >> 1) + ((s2i & 1) ? 0.75f : 0.25f), bw, sx);
        int lo, hi; float w0, w1;
        axis_terms(pos, W_, lo, hi, w0, w1);
        int xb; float v0, v1;
        if (lo == W_ - 1) { xb = W_ - 2; v0 = 0.0f; v1 = w0 + w1; }
        else              { xb = lo;     v0 = w0;   v1 = w1; }
        __half2 s0 = __float2half2_rn(v0);
        __half2 s1 = __float2half2_rn(v1);
        sg[14 + s2i] = make_int4(xb * PIXU4,
                                 *(int*)&s0, *(int*)&s1, 0);
    }
    __syncthreads();

    const int warp = tid >> 5;
    const int lane = tid & 31;
    const uint4* base = (const uint4*)g_xt + (size_t)b * (HW_ * PIXU4) + lane;

    for (int bin = warp; bin < 49; bin += 8) {
        int ph = (bin * 147) >> 10;       // bin / 7 for bin < 49
        int pw = bin - ph * 7;

        int4 gy0 = sg[2 * ph];
        int4 gy1 = sg[2 * ph + 1];
        int4 gx0 = sg[14 + 2 * pw];
        int4 gx1 = sg[14 + 2 * pw + 1];

        const int xoff = gx0.x;
        const int dx   = gx1.x - gx0.x;
        const __half2 w0s = *(__half2*)&gx0.y;
        const __half2 w1s = *(__half2*)&gx0.z;
        const __half2 w2s = *(__half2*)&gx1.y;
        const __half2 w3s = *(__half2*)&gx1.z;

        const int   roff[4] = {gy0.x, gy0.y, gy1.x, gy1.y};
        const float wy[4]   = {__int_as_float(gy0.z), __int_as_float(gy0.w),
                               __int_as_float(gy1.z), __int_as_float(gy1.w)};

        float acc[8] = {0.f, 0.f, 0.f, 0.f, 0.f, 0.f, 0.f, 0.f};

#pragma unroll
        for (int rr = 0; rr < 4; rr++) {
            const uint4* pr = base + roff[rr] + xoff;
            uint4 t0 = __ldg(pr);
            uint4 t1 = __ldg(pr + PIXU4);
            uint4 t2 = __ldg(pr + dx);
            uint4 t3 = __ldg(pr + dx + PIXU4);
            const __half2* a0 = (const __half2*)&t0;
            const __half2* a1 = (const __half2*)&t1;
            const __half2* a2 = (const __half2*)&t2;
            const __half2* a3 = (const __half2*)&t3;
            float wyr = wy[rr];
#pragma unroll
            for (int m = 0; m < 4; m++) {
                __half2 hv = __hmul2(w0s, a0[m]);
                hv = __hfma2(w1s, a1[m], hv);
                hv = __hfma2(w2s, a2[m], hv);
                hv = __hfma2(w3s, a3[m], hv);
                float2 f2 = __half22float2(hv);
                acc[2 * m]     = fmaf(wyr, f2.x, acc[2 * m]);
                acc[2 * m + 1] = fmaf(wyr, f2.y, acc[2 * m + 1]);
            }
        }

        // acc[j] is channel 32j + lane -> stride-49 STS, conflict-free
        float* so = sout + lane * 49 + bin;
#pragma unroll
        for (int j = 0; j < 8; j++)
            so[j * (32 * 49)] = acc[j];
    }
    __syncthreads();

    float4* op = (float4*)(out + (size_t)r * (C_ * 49));
    const float4* sp = (const float4*)sout;
    for (int i = tid; i < C_ * 49 / 4; i += 256)
        op[i] = sp[i];
}

extern "C" void kernel_launch(void* const* d_in, const int* in_sizes, int n_in,
                              void* d_out, int out_size) {
    const float* x    = (const float*)d_in[0];
    const float* rois = (const float*)d_in[1];
    float* out = (float*)d_out;

    const int msmem = C_ * 49 * 4;            // 50176 B
    cudaFuncSetAttribute(roi_fp16,
                         cudaFuncAttributeMaxDynamicSharedMemorySize, msmem);

    transpose_kernel<<<8 * H_, TTHR>>>(x);
    roi_fp16<<<R_, 256, msmem>>>(rois, out);
}